// round 1
// baseline (speedup 1.0000x reference)
#include <cuda_runtime.h>
#include <math.h>
#include <stdint.h>

#define Lq 1024
#define Rr 8192
#define Ff 64
#define CH 64
#define RC (Rr/CH)   // 128

// ---------------- scratch (device globals; no allocs allowed) ----------------
__device__ float g_atnT[8388608];           // [Rr][Lq]  32MB, L2-resident
__device__ float g_ligx[Lq], g_ligy[Lq], g_ligz[Lq];
__device__ float g_recx[Rr], g_recy[Rr], g_recz[Rr];
__device__ float g_nlx[Lq], g_nly[Lq], g_nlz[Lq];
__device__ float g_pr[9], g_tr[3], g_Qm[9], g_Rm[9];
__device__ float g_psw[CH*Lq], g_pswx[CH*Lq], g_pswy[CH*Lq], g_pswz[CH*Lq];
__device__ float g_red12[8][12];

__device__ __forceinline__ float frcp(float x) {
    float y; asm("rcp.approx.f32 %0, %1;" : "=f"(y) : "f"(x)); return y;
}

// LAPACK-convention Householder QR of a 3x3 (geqrf+orgqr signs).
__device__ void qr3(const float* A, float* Q, float* Rm) {
    float M[9];
    #pragma unroll
    for (int i = 0; i < 9; i++) M[i] = A[i];
    float Qa[9] = {1.f,0.f,0.f, 0.f,1.f,0.f, 0.f,0.f,1.f};
    #pragma unroll
    for (int k = 0; k < 2; k++) {
        float alpha = M[k*3+k];
        float xn2 = 0.f;
        for (int j = k+1; j < 3; j++) xn2 += M[j*3+k]*M[j*3+k];
        if (xn2 == 0.f) continue;               // tau=0, H=I (LAPACK)
        float nrm  = sqrtf(alpha*alpha + xn2);
        float beta = (alpha >= 0.f) ? -nrm : nrm;   // -sign(alpha)*norm
        float v[3] = {0.f,0.f,0.f};
        v[k] = 1.f;
        float denom = alpha - beta;
        for (int j = k+1; j < 3; j++) v[j] = M[j*3+k] / denom;
        float tau = (beta - alpha) / beta;
        for (int c = k; c < 3; c++) {
            float s = 0.f;
            for (int j = k; j < 3; j++) s += v[j]*M[j*3+c];
            s *= tau;
            for (int j = k; j < 3; j++) M[j*3+c] -= s*v[j];
        }
        M[k*3+k] = beta;
        for (int j = k+1; j < 3; j++) M[j*3+k] = 0.f;
        for (int i = 0; i < 3; i++) {
            float s = 0.f;
            for (int j = k; j < 3; j++) s += Qa[i*3+j]*v[j];
            s *= tau;
            for (int j = k; j < 3; j++) Qa[i*3+j] -= s*v[j];
        }
    }
    #pragma unroll
    for (int i = 0; i < 9; i++) { Q[i] = Qa[i]; Rm[i] = M[i]; }
}

// ---------------- prep: center lig coords, copy params ----------------
__global__ void k_prep_lig(const float* __restrict__ lig_coord,
                           const float* __restrict__ pre_rot,
                           const float* __restrict__ trans) {
    int l = threadIdx.x;
    float x = lig_coord[3*l], y = lig_coord[3*l+1], z = lig_coord[3*l+2];
    float sx = x, sy = y, sz = z;
    #pragma unroll
    for (int o = 16; o > 0; o >>= 1) {
        sx += __shfl_down_sync(0xffffffffu, sx, o);
        sy += __shfl_down_sync(0xffffffffu, sy, o);
        sz += __shfl_down_sync(0xffffffffu, sz, o);
    }
    __shared__ float sred[3][32];
    int warp = l >> 5, lane = l & 31;
    if (lane == 0) { sred[0][warp] = sx; sred[1][warp] = sy; sred[2][warp] = sz; }
    __syncthreads();
    if (warp == 0) {
        sx = sred[0][lane]; sy = sred[1][lane]; sz = sred[2][lane];
        #pragma unroll
        for (int o = 16; o > 0; o >>= 1) {
            sx += __shfl_down_sync(0xffffffffu, sx, o);
            sy += __shfl_down_sync(0xffffffffu, sy, o);
            sz += __shfl_down_sync(0xffffffffu, sz, o);
        }
        if (lane == 0) {
            sred[0][0] = sx * (1.f/Lq); sred[1][0] = sy * (1.f/Lq); sred[2][0] = sz * (1.f/Lq);
        }
    }
    __syncthreads();
    g_ligx[l] = x - sred[0][0];
    g_ligy[l] = y - sred[1][0];
    g_ligz[l] = z - sred[2][0];
    if (l < 9) g_pr[l] = pre_rot[l];
    if (l < 3) g_tr[l] = trans[l] * 4.0f;   // TRANS_DIST
}

__global__ void k_prep_rec(const float* __restrict__ rec_coord) {
    int t = threadIdx.x;
    float xs[8], ys[8], zs[8];
    float sx = 0.f, sy = 0.f, sz = 0.f;
    #pragma unroll
    for (int i = 0; i < 8; i++) {
        int r = i*1024 + t;
        xs[i] = rec_coord[3*r]; ys[i] = rec_coord[3*r+1]; zs[i] = rec_coord[3*r+2];
        sx += xs[i]; sy += ys[i]; sz += zs[i];
    }
    #pragma unroll
    for (int o = 16; o > 0; o >>= 1) {
        sx += __shfl_down_sync(0xffffffffu, sx, o);
        sy += __shfl_down_sync(0xffffffffu, sy, o);
        sz += __shfl_down_sync(0xffffffffu, sz, o);
    }
    __shared__ float sred[3][32];
    int warp = t >> 5, lane = t & 31;
    if (lane == 0) { sred[0][warp] = sx; sred[1][warp] = sy; sred[2][warp] = sz; }
    __syncthreads();
    if (warp == 0) {
        sx = sred[0][lane]; sy = sred[1][lane]; sz = sred[2][lane];
        #pragma unroll
        for (int o = 16; o > 0; o >>= 1) {
            sx += __shfl_down_sync(0xffffffffu, sx, o);
            sy += __shfl_down_sync(0xffffffffu, sy, o);
            sz += __shfl_down_sync(0xffffffffu, sz, o);
        }
        if (lane == 0) {
            sred[0][0] = sx * (1.f/Rr); sred[1][0] = sy * (1.f/Rr); sred[2][0] = sz * (1.f/Rr);
        }
    }
    __syncthreads();
    float mx = sred[0][0], my = sred[1][0], mz = sred[2][0];
    #pragma unroll
    for (int i = 0; i < 8; i++) {
        int r = i*1024 + t;
        g_recx[r] = xs[i] - mx; g_recy[r] = ys[i] - my; g_recz[r] = zs[i] - mz;
    }
}

// ---------------- atnT[r][l] = dot(lig_feat[l], rec_feat[r]) ----------------
// tile 64r x 64l, 256 threads, 4x4 register tile, XOR-swizzled smem.
__global__ void __launch_bounds__(256) k_atn(const float* __restrict__ lig_feat,
                                             const float* __restrict__ rec_feat) {
    __shared__ float4 ligs4[64*16];
    __shared__ float4 recs4[64*16];
    int tid = threadIdx.x;
    int tx = tid & 15;       // l-lane
    int ty = tid >> 4;       // r-group
    int r0 = blockIdx.x * 64;
    int l0 = blockIdx.y * 64;
    const float4* ligf4 = (const float4*)lig_feat;
    const float4* recf4 = (const float4*)rec_feat;
    #pragma unroll
    for (int i = 0; i < 4; i++) {
        int idx = i*256 + tid;
        int row = idx >> 4;
        int f4  = idx & 15;
        ligs4[row*16 + (f4 ^ (row & 7))] = ligf4[(size_t)(l0+row)*16 + f4];
        recs4[row*16 + (f4 ^ (row & 7))] = recf4[(size_t)(r0+row)*16 + f4];
    }
    __syncthreads();
    float acc[4][4];
    #pragma unroll
    for (int i = 0; i < 4; i++)
        #pragma unroll
        for (int j = 0; j < 4; j++) acc[i][j] = 0.f;

    #pragma unroll
    for (int f4 = 0; f4 < 16; f4++) {
        float4 a[4], b[4];
        #pragma unroll
        for (int i = 0; i < 4; i++) {
            int row = tx + 16*i;
            a[i] = ligs4[row*16 + (f4 ^ (row & 7))];
        }
        #pragma unroll
        for (int j = 0; j < 4; j++) {
            int row = ty*4 + j;
            b[j] = recs4[row*16 + (f4 ^ (row & 7))];
        }
        #pragma unroll
        for (int i = 0; i < 4; i++)
            #pragma unroll
            for (int j = 0; j < 4; j++) {
                acc[i][j] = fmaf(a[i].x, b[j].x, acc[i][j]);
                acc[i][j] = fmaf(a[i].y, b[j].y, acc[i][j]);
                acc[i][j] = fmaf(a[i].z, b[j].z, acc[i][j]);
                acc[i][j] = fmaf(a[i].w, b[j].w, acc[i][j]);
            }
    }
    #pragma unroll
    for (int j = 0; j < 4; j++) {
        size_t rowbase = (size_t)(r0 + ty*4 + j) * Lq + l0;
        #pragma unroll
        for (int i = 0; i < 4; i++)
            g_atnT[rowbase + tx + 16*i] = acc[i][j];
    }
}

// ---------------- forward for step 0 ----------------
__global__ void k_first(float* __restrict__ out) {
    __shared__ float sQ[9], sTr[3];
    int l = threadIdx.x;
    if (l == 0) {
        float Q[9], Rm[9], A[9];
        #pragma unroll
        for (int i = 0; i < 9; i++) A[i] = g_pr[i];
        qr3(A, Q, Rm);
        #pragma unroll
        for (int i = 0; i < 9; i++) { g_Qm[i] = Q[i]; g_Rm[i] = Rm[i]; sQ[i] = Q[i]; }
        #pragma unroll
        for (int i = 0; i < 3; i++) sTr[i] = g_tr[i];
    }
    __syncthreads();
    float x = g_ligx[l], y = g_ligy[l], z = g_ligz[l];
    float nx = sQ[0]*x + sQ[1]*y + sQ[2]*z + sTr[0];
    float ny = sQ[3]*x + sQ[4]*y + sQ[5]*z + sTr[1];
    float nz = sQ[6]*x + sQ[7]*y + sQ[8]*z + sTr[2];
    g_nlx[l] = nx; g_nly[l] = ny; g_nlz[l] = nz;
    out[3*l] = nx; out[3*l+1] = ny; out[3*l+2] = nz;
}

// ---------------- pair kernel: per-(l,chunk) partial sums ----------------
__global__ void __launch_bounds__(256) k_pairs() {
    __shared__ float sx[RC], sy[RC], sz[RC];
    int l  = blockIdx.x * 256 + threadIdx.x;
    int r0 = blockIdx.y * RC;
    if (threadIdx.x < RC) {
        sx[threadIdx.x] = g_recx[r0 + threadIdx.x];
        sy[threadIdx.x] = g_recy[r0 + threadIdx.x];
        sz[threadIdx.x] = g_recz[r0 + threadIdx.x];
    }
    __syncthreads();
    float nx = g_nlx[l], ny = g_nly[l], nz = g_nlz[l];
    float sw = 0.f, swx = 0.f, swy = 0.f, swz = 0.f;
    const float* ap = g_atnT + (size_t)r0 * Lq + l;
    #pragma unroll 8
    for (int j = 0; j < RC; j++) {
        float a  = ap[(size_t)j * Lq];
        float rx = sx[j], ry = sy[j], rz = sz[j];
        float dx = nx - rx, dy = ny - ry, dz = nz - rz;
        float d2 = fmaf(dx, dx, fmaf(dy, dy, dz*dz));
        float inv = frcp(d2);
        float w = a * inv * inv;                 // atn/d2^2
        sw += w;
        swx = fmaf(w, rx, swx);
        swy = fmaf(w, ry, swy);
        swz = fmaf(w, rz, swz);
    }
    int o = blockIdx.y * Lq + l;
    g_psw[o] = sw; g_pswx[o] = swx; g_pswy[o] = swy; g_pswz[o] = swz;
}

// ---------------- stage-1 reduce: chunks -> per-block 12 sums ----------------
__global__ void k_red() {
    int b = blockIdx.x;          // 0..7
    int t = threadIdx.x;         // 0..127
    int l = b*128 + t;
    float sw = 0.f, swx = 0.f, swy = 0.f, swz = 0.f;
    #pragma unroll 8
    for (int c = 0; c < CH; c++) {
        int o = c*Lq + l;
        sw += g_psw[o]; swx += g_pswx[o]; swy += g_pswy[o]; swz += g_pswz[o];
    }
    const float Cc = -2.f / 8388608.f;           // -2/(L*R)
    float nx = g_nlx[l], ny = g_nly[l], nz = g_nlz[l];
    float gx = Cc * (sw*nx - swx);
    float gy = Cc * (sw*ny - swy);
    float gz = Cc * (sw*nz - swz);
    float lx = g_ligx[l], ly = g_ligy[l], lz = g_ligz[l];
    float v[12] = {gx, gy, gz,
                   gx*lx, gx*ly, gx*lz,
                   gy*lx, gy*ly, gy*lz,
                   gz*lx, gz*ly, gz*lz};
    #pragma unroll
    for (int k = 0; k < 12; k++)
        #pragma unroll
        for (int o = 16; o > 0; o >>= 1)
            v[k] += __shfl_down_sync(0xffffffffu, v[k], o);
    __shared__ float sh[4][12];
    int warp = t >> 5, lane = t & 31;
    if (lane == 0)
        #pragma unroll
        for (int k = 0; k < 12; k++) sh[warp][k] = v[k];
    __syncthreads();
    if (t < 12) g_red12[b][t] = sh[0][t] + sh[1][t] + sh[2][t] + sh[3][t];
}

// ---------------- finalize: QR backward, param update, next forward ----------
__global__ void k_update(float* __restrict__ out_next) {
    __shared__ float sQ[9], sTr[3];
    int l = threadIdx.x;
    if (l == 0) {
        float t[12];
        #pragma unroll
        for (int k = 0; k < 12; k++) {
            float s = 0.f;
            #pragma unroll
            for (int b = 0; b < 8; b++) s += g_red12[b][k];
            t[k] = s;
        }
        float Q[9], Rm[9];
        #pragma unroll
        for (int i = 0; i < 9; i++) { Q[i] = g_Qm[i]; Rm[i] = g_Rm[i]; }
        // G[i][j] = t[3+3i+j]  (cotangent on Q)
        float G0=t[3],G1=t[4],G2=t[5],G3=t[6],G4=t[7],G5=t[8],G6=t[9],G7=t[10],G8=t[11];
        // S = Q^T G (only off-diagonals needed)
        float S10 = Q[1]*G0 + Q[4]*G3 + Q[7]*G6;
        float S01 = Q[0]*G1 + Q[3]*G4 + Q[6]*G7;
        float S20 = Q[2]*G0 + Q[5]*G3 + Q[8]*G6;
        float S02 = Q[0]*G2 + Q[3]*G5 + Q[6]*G8;
        float S21 = Q[2]*G1 + Q[5]*G4 + Q[8]*G7;
        float S12 = Q[1]*G2 + Q[4]*G5 + Q[7]*G8;
        float b10 = S10 - S01, b20 = S20 - S02, b21 = S21 - S12;
        // T = B R^{-T}; B strictly lower
        float T10 = b10 / Rm[0];
        float T21 = b21 / Rm[4];
        float T20 = (b20 - T21*Rm[1]) / Rm[0];
        // Abar = Q * T
        float A[9];
        #pragma unroll
        for (int i = 0; i < 3; i++) {
            float a0 = Q[i*3+1]*T10 + Q[i*3+2]*T20;
            float a1 = Q[i*3+2]*T21;
            A[i*3+0] = g_pr[i*3+0] - a0;      // ROT_LR = 1
            A[i*3+1] = g_pr[i*3+1] - a1;
            A[i*3+2] = g_pr[i*3+2];
        }
        float tr[3];
        #pragma unroll
        for (int i = 0; i < 3; i++) tr[i] = g_tr[i] - 0.1f * t[i];   // TRANS_LR
        #pragma unroll
        for (int i = 0; i < 9; i++) g_pr[i] = A[i];
        #pragma unroll
        for (int i = 0; i < 3; i++) { g_tr[i] = tr[i]; sTr[i] = tr[i]; }
        float Qn[9], Rn[9];
        qr3(A, Qn, Rn);
        #pragma unroll
        for (int i = 0; i < 9; i++) { g_Qm[i] = Qn[i]; g_Rm[i] = Rn[i]; sQ[i] = Qn[i]; }
    }
    __syncthreads();
    float x = g_ligx[l], y = g_ligy[l], z = g_ligz[l];
    float nx = sQ[0]*x + sQ[1]*y + sQ[2]*z + sTr[0];
    float ny = sQ[3]*x + sQ[4]*y + sQ[5]*z + sTr[1];
    float nz = sQ[6]*x + sQ[7]*y + sQ[8]*z + sTr[2];
    g_nlx[l] = nx; g_nly[l] = ny; g_nlz[l] = nz;
    out_next[3*l] = nx; out_next[3*l+1] = ny; out_next[3*l+2] = nz;
}

extern "C" void kernel_launch(void* const* d_in, const int* in_sizes, int n_in,
                              void* d_out, int out_size) {
    const float* lig_feat  = (const float*)d_in[0];
    const float* rec_feat  = (const float*)d_in[1];
    const float* lig_coord = (const float*)d_in[2];
    const float* rec_coord = (const float*)d_in[3];
    const float* pre_rot   = (const float*)d_in[4];
    const float* trans     = (const float*)d_in[5];
    float* out = (float*)d_out;

    k_prep_lig<<<1, 1024>>>(lig_coord, pre_rot, trans);
    k_prep_rec<<<1, 1024>>>(rec_coord);
    k_atn<<<dim3(Rr/64, Lq/64), 256>>>(lig_feat, rec_feat);
    k_first<<<1, 1024>>>(out);
    // steps 0..6 compute grads + update + emit forward of step s+1.
    // step 7's forward is emitted by step 6's k_update; no gradient needed after.
    for (int s = 0; s < 7; s++) {
        k_pairs<<<dim3(Lq/256, CH), 256>>>();
        k_red<<<8, 128>>>();
        k_update<<<1, 1024>>>(out + (size_t)(s+1)*3*Lq);
    }
}

// round 2
// speedup vs baseline: 1.7971x; 1.7971x over previous
#include <cuda_runtime.h>
#include <math.h>
#include <stdint.h>

#define Lq 1024
#define Rr 8192
#define NB 128
#define NT 256

typedef unsigned long long u64;

// ---------------- scratch (device globals; no allocs allowed) ----------------
__device__ float g_atn[(size_t)Lq * Rr];     // [l][r] 32MB, L2-resident
__device__ float g_part[NB][12];
__device__ float g_upd[12];                  // Q(9) + tr(3) broadcast
__device__ unsigned g_cnt;                   // grid barrier counter (self-resetting)
__device__ unsigned g_sense;                 // grid barrier sense

__device__ __forceinline__ float frcp(float x) {
    float y; asm("rcp.approx.f32 %0, %1;" : "=f"(y) : "f"(x)); return y;
}

// packed f32x2 helpers (sm_100+)
__device__ __forceinline__ u64 pk2(float lo, float hi) {
    u64 r; asm("mov.b64 %0, {%1, %2};" : "=l"(r) : "f"(lo), "f"(hi)); return r;
}
__device__ __forceinline__ void up2(u64 v, float& a, float& b) {
    asm("mov.b64 {%0, %1}, %2;" : "=f"(a), "=f"(b) : "l"(v));
}
__device__ __forceinline__ u64 add2(u64 a, u64 b) {
    u64 d; asm("add.rn.f32x2 %0, %1, %2;" : "=l"(d) : "l"(a), "l"(b)); return d;
}
__device__ __forceinline__ u64 mul2(u64 a, u64 b) {
    u64 d; asm("mul.rn.f32x2 %0, %1, %2;" : "=l"(d) : "l"(a), "l"(b)); return d;
}
__device__ __forceinline__ u64 fma2(u64 a, u64 b, u64 c) {
    u64 d; asm("fma.rn.f32x2 %0, %1, %2, %3;" : "=l"(d) : "l"(a), "l"(b), "l"(c)); return d;
}

// sense-reversing grid barrier; ends each launch back at (cnt=0, sense flipped),
// and sense is re-read at kernel start, so graph replays stay consistent.
__device__ __forceinline__ void gridbar(unsigned& sense) {
    __syncthreads();
    if (threadIdx.x == 0) {
        unsigned ns = sense ^ 1u;
        __threadfence();
        unsigned old = atomicAdd(&g_cnt, 1u);
        if (old == NB - 1u) {
            atomicExch(&g_cnt, 0u);
            asm volatile("st.release.gpu.u32 [%0], %1;" :: "l"(&g_sense), "r"(ns) : "memory");
        } else {
            unsigned v;
            do {
                asm volatile("ld.acquire.gpu.u32 %0, [%1];" : "=r"(v) : "l"(&g_sense) : "memory");
            } while (v != ns);
        }
    }
    __syncthreads();
    sense ^= 1u;
}

// LAPACK-convention Householder QR of a 3x3 (geqrf+orgqr signs).
__device__ void qr3(const float* A, float* Q, float* Rm) {
    float M[9];
    #pragma unroll
    for (int i = 0; i < 9; i++) M[i] = A[i];
    float Qa[9] = {1.f,0.f,0.f, 0.f,1.f,0.f, 0.f,0.f,1.f};
    #pragma unroll
    for (int k = 0; k < 2; k++) {
        float alpha = M[k*3+k];
        float xn2 = 0.f;
        for (int j = k+1; j < 3; j++) xn2 += M[j*3+k]*M[j*3+k];
        if (xn2 == 0.f) continue;               // tau=0, H=I (LAPACK)
        float nrm  = sqrtf(alpha*alpha + xn2);
        float beta = (alpha >= 0.f) ? -nrm : nrm;   // -sign(alpha)*norm
        float v[3] = {0.f,0.f,0.f};
        v[k] = 1.f;
        float denom = alpha - beta;
        for (int j = k+1; j < 3; j++) v[j] = M[j*3+k] / denom;
        float tau = (beta - alpha) / beta;
        for (int c = k; c < 3; c++) {
            float s = 0.f;
            for (int j = k; j < 3; j++) s += v[j]*M[j*3+c];
            s *= tau;
            for (int j = k; j < 3; j++) M[j*3+c] -= s*v[j];
        }
        M[k*3+k] = beta;
        for (int j = k+1; j < 3; j++) M[j*3+k] = 0.f;
        for (int i = 0; i < 3; i++) {
            float s = 0.f;
            for (int j = k; j < 3; j++) s += Qa[i*3+j]*v[j];
            s *= tau;
            for (int j = k; j < 3; j++) Qa[i*3+j] -= s*v[j];
        }
    }
    #pragma unroll
    for (int i = 0; i < 9; i++) { Q[i] = Qa[i]; Rm[i] = M[i]; }
}

__device__ __forceinline__ float blockSum(float v, float* s8) {
    #pragma unroll
    for (int o = 16; o > 0; o >>= 1) v += __shfl_down_sync(0xffffffffu, v, o);
    __syncthreads();                       // protect s8 from previous use
    if ((threadIdx.x & 31) == 0) s8[threadIdx.x >> 5] = v;
    __syncthreads();
    float t = s8[0];
    #pragma unroll
    for (int i = 1; i < 8; i++) t += s8[i];
    return t;
}

// ---------------- atn[l][r] = dot(lig_feat[l], rec_feat[r]) ----------------
// tile 64l x 64r, 256 threads, 4x4 register tile, XOR-swizzled smem.
__global__ void __launch_bounds__(256) k_atn(const float* __restrict__ lig_feat,
                                             const float* __restrict__ rec_feat) {
    __shared__ float4 ligs4[64*16];
    __shared__ float4 recs4[64*16];
    int tid = threadIdx.x;
    int tx = tid & 15;       // r-lane
    int ty = tid >> 4;       // l-group
    int r0 = blockIdx.x * 64;
    int l0 = blockIdx.y * 64;
    const float4* ligf4 = (const float4*)lig_feat;
    const float4* recf4 = (const float4*)rec_feat;
    #pragma unroll
    for (int i = 0; i < 4; i++) {
        int idx = i*256 + tid;
        int row = idx >> 4;
        int f4  = idx & 15;
        ligs4[row*16 + (f4 ^ (row & 7))] = ligf4[(size_t)(l0+row)*16 + f4];
        recs4[row*16 + (f4 ^ (row & 7))] = recf4[(size_t)(r0+row)*16 + f4];
    }
    __syncthreads();
    float acc[4][4];
    #pragma unroll
    for (int i = 0; i < 4; i++)
        #pragma unroll
        for (int j = 0; j < 4; j++) acc[i][j] = 0.f;

    #pragma unroll
    for (int f4 = 0; f4 < 16; f4++) {
        float4 a[4], b[4];
        #pragma unroll
        for (int i = 0; i < 4; i++) {         // rec rows (coalesced output dim)
            int row = tx + 16*i;
            a[i] = recs4[row*16 + (f4 ^ (row & 7))];
        }
        #pragma unroll
        for (int j = 0; j < 4; j++) {         // lig rows
            int row = ty*4 + j;
            b[j] = ligs4[row*16 + (f4 ^ (row & 7))];
        }
        #pragma unroll
        for (int i = 0; i < 4; i++)
            #pragma unroll
            for (int j = 0; j < 4; j++) {
                acc[i][j] = fmaf(a[i].x, b[j].x, acc[i][j]);
                acc[i][j] = fmaf(a[i].y, b[j].y, acc[i][j]);
                acc[i][j] = fmaf(a[i].z, b[j].z, acc[i][j]);
                acc[i][j] = fmaf(a[i].w, b[j].w, acc[i][j]);
            }
    }
    #pragma unroll
    for (int j = 0; j < 4; j++) {
        size_t rowbase = (size_t)(l0 + ty*4 + j) * Rr + r0;
        #pragma unroll
        for (int i = 0; i < 4; i++)
            g_atn[rowbase + tx + 16*i] = acc[i][j];
    }
}

// ---------------- persistent kernel: preps + all 8 steps ----------------
__global__ void __launch_bounds__(NT, 1) k_steps(const float* __restrict__ lig_coord,
                                                 const float* __restrict__ rec_coord,
                                                 const float* __restrict__ pre_rot,
                                                 const float* __restrict__ trans,
                                                 float* __restrict__ out) {
    extern __shared__ float sm[];
    float* srx = sm;             // negated-centered rec x   [Rr]
    float* sry = sm + Rr;
    float* srz = sm + 2*Rr;
    __shared__ float s_red[8];
    __shared__ float s_part[8][12];
    __shared__ float s_scr[96];

    int tid = threadIdx.x, b = blockIdx.x;
    int w = tid >> 5, lane = tid & 31;
    int l = b * 8 + w;           // this warp's ligand atom

    unsigned sense;
    { volatile unsigned* gs = &g_sense; sense = *gs; }

    // ---- rec: load raw to smem + mean, then center (negated) ----
    float sx = 0.f, sy = 0.f, sz = 0.f;
    for (int i = tid; i < Rr; i += NT) {
        float x = rec_coord[3*i], y = rec_coord[3*i+1], z = rec_coord[3*i+2];
        srx[i] = x; sry[i] = y; srz[i] = z;
        sx += x; sy += y; sz += z;
    }
    float mx = blockSum(sx, s_red) * (1.f/Rr);
    float my = blockSum(sy, s_red) * (1.f/Rr);
    float mz = blockSum(sz, s_red) * (1.f/Rr);
    __syncthreads();
    for (int i = tid; i < Rr; i += NT) {
        srx[i] = mx - srx[i];    // -(x - mean)
        sry[i] = my - sry[i];
        srz[i] = mz - srz[i];
    }

    // ---- lig mean + this warp's centered coords ----
    float lsx = 0.f, lsy = 0.f, lsz = 0.f;
    for (int i = tid; i < Lq; i += NT) {
        lsx += lig_coord[3*i]; lsy += lig_coord[3*i+1]; lsz += lig_coord[3*i+2];
    }
    float mlx = blockSum(lsx, s_red) * (1.f/Lq);
    float mly = blockSum(lsy, s_red) * (1.f/Lq);
    float mlz = blockSum(lsz, s_red) * (1.f/Lq);
    float lx = lig_coord[3*l] - mlx;
    float ly = lig_coord[3*l+1] - mly;
    float lz = lig_coord[3*l+2] - mlz;

    // ---- initial params + QR (block 0, thread 0 holds optimizer state) ----
    float pr[9], trv[3], Q[9], Rm[9];
    if (b == 0 && tid == 0) {
        #pragma unroll
        for (int i = 0; i < 9; i++) pr[i] = pre_rot[i];
        #pragma unroll
        for (int i = 0; i < 3; i++) trv[i] = trans[i] * 4.0f;   // TRANS_DIST
        qr3(pr, Q, Rm);
        #pragma unroll
        for (int i = 0; i < 9; i++) g_upd[i] = Q[i];
        #pragma unroll
        for (int i = 0; i < 3; i++) g_upd[9+i] = trv[i];
    }
    gridbar(sense);   // #1: g_upd visible everywhere; smem centered rec ready

    // ---- forward for step 0 ----
    float nx, ny, nz;
    u64 nx2, ny2, nz2;
    {
        const volatile float* up = g_upd;
        float q0=up[0],q1=up[1],q2=up[2],q3=up[3],q4=up[4],q5=up[5],q6=up[6],q7=up[7],q8=up[8];
        float t0=up[9],t1=up[10],t2=up[11];
        nx = q0*lx + q1*ly + q2*lz + t0;
        ny = q3*lx + q4*ly + q5*lz + t1;
        nz = q6*lx + q7*ly + q8*lz + t2;
        if (lane == 0) { float* o0 = out + 3*l; o0[0]=nx; o0[1]=ny; o0[2]=nz; }
        nx2 = pk2(nx, nx); ny2 = pk2(ny, ny); nz2 = pk2(nz, nz);
    }

    const u64* ap2 = (const u64*)(g_atn + (size_t)l * Rr);
    const u64* rx2 = (const u64*)srx;
    const u64* ry2 = (const u64*)sry;
    const u64* rz2 = (const u64*)srz;

    for (int s = 0; s < 7; s++) {
        // ---- pair loop: 2 r's per lane-iteration, packed f32x2 ----
        u64 sw2 = 0ull, accx = 0ull, accy = 0ull, accz = 0ull;
        #pragma unroll 4
        for (int it = 0; it < Rr/64; it++) {      // 128 iters
            int idx = it*32 + lane;
            u64 a2  = ap2[idx];
            u64 nrx = rx2[idx], nry = ry2[idx], nrz = rz2[idx];
            u64 dx = add2(nx2, nrx);
            u64 dy = add2(ny2, nry);
            u64 dz = add2(nz2, nrz);
            u64 d2 = mul2(dz, dz);
            d2 = fma2(dy, dy, d2);
            d2 = fma2(dx, dx, d2);
            float dlo, dhi; up2(d2, dlo, dhi);
            u64 inv2 = pk2(frcp(dlo), frcp(dhi));
            u64 i4 = mul2(inv2, inv2);
            u64 w2 = mul2(a2, i4);                // atn/d2^2
            sw2  = add2(sw2, w2);
            accx = fma2(w2, nrx, accx);           // = -sum(w*rx)
            accy = fma2(w2, nry, accy);
            accz = fma2(w2, nrz, accz);
        }
        float sw, t1v, ax, ay, az, t2v;
        up2(sw2, sw, t1v);  sw += t1v;
        up2(accx, ax, t2v); ax += t2v;
        up2(accy, ay, t2v); ay += t2v;
        up2(accz, az, t2v); az += t2v;
        #pragma unroll
        for (int o = 16; o > 0; o >>= 1) {
            sw += __shfl_down_sync(0xffffffffu, sw, o);
            ax += __shfl_down_sync(0xffffffffu, ax, o);
            ay += __shfl_down_sync(0xffffffffu, ay, o);
            az += __shfl_down_sync(0xffffffffu, az, o);
        }
        if (lane == 0) {
            const float Cc = -2.f / 8388608.f;    // -2/(L*R)
            float gx = Cc * (sw*nx + ax);         // ax = -sum(w*rx)
            float gy = Cc * (sw*ny + ay);
            float gz = Cc * (sw*nz + az);
            s_part[w][0] = gx;    s_part[w][1] = gy;    s_part[w][2] = gz;
            s_part[w][3] = gx*lx; s_part[w][4] = gx*ly; s_part[w][5] = gx*lz;
            s_part[w][6] = gy*lx; s_part[w][7] = gy*ly; s_part[w][8] = gy*lz;
            s_part[w][9] = gz*lx; s_part[w][10]= gz*ly; s_part[w][11]= gz*lz;
        }
        __syncthreads();
        if (tid < 12) {
            float t = 0.f;
            #pragma unroll
            for (int ww = 0; ww < 8; ww++) t += s_part[ww][tid];
            g_part[b][tid] = t;
        }
        gridbar(sense);   // partials visible

        // ---- block 0: global reduce + QR backward + update + next QR ----
        if (b == 0) {
            float v[12];
            #pragma unroll
            for (int k = 0; k < 12; k++)
                v[k] = (tid < NB) ? ((volatile float*)g_part)[tid*12 + k] : 0.f;
            #pragma unroll
            for (int k = 0; k < 12; k++) {
                float x = v[k];
                #pragma unroll
                for (int o = 16; o > 0; o >>= 1) x += __shfl_down_sync(0xffffffffu, x, o);
                if (lane == 0) s_scr[w*12 + k] = x;
            }
            __syncthreads();
            if (tid == 0) {
                float t[12];
                #pragma unroll
                for (int k = 0; k < 12; k++) {
                    float ssum = 0.f;
                    #pragma unroll
                    for (int ww = 0; ww < 8; ww++) ssum += s_scr[ww*12 + k];
                    t[k] = ssum;
                }
                // G[i][j] = t[3+3i+j] (cotangent on Q)
                float G0=t[3],G1=t[4],G2=t[5],G3=t[6],G4=t[7],G5=t[8],G6=t[9],G7=t[10],G8=t[11];
                float S10 = Q[1]*G0 + Q[4]*G3 + Q[7]*G6;
                float S01 = Q[0]*G1 + Q[3]*G4 + Q[6]*G7;
                float S20 = Q[2]*G0 + Q[5]*G3 + Q[8]*G6;
                float S02 = Q[0]*G2 + Q[3]*G5 + Q[6]*G8;
                float S21 = Q[2]*G1 + Q[5]*G4 + Q[8]*G7;
                float S12 = Q[1]*G2 + Q[4]*G5 + Q[7]*G8;
                float b10 = S10 - S01, b20 = S20 - S02, b21 = S21 - S12;
                float T10 = b10 / Rm[0];
                float T21 = b21 / Rm[4];
                float T20 = (b20 - T21*Rm[1]) / Rm[0];
                #pragma unroll
                for (int i = 0; i < 3; i++) {
                    float a0 = Q[i*3+1]*T10 + Q[i*3+2]*T20;
                    float a1 = Q[i*3+2]*T21;
                    pr[i*3+0] -= a0;              // ROT_LR = 1
                    pr[i*3+1] -= a1;
                }
                #pragma unroll
                for (int i = 0; i < 3; i++) trv[i] -= 0.1f * t[i];   // TRANS_LR
                qr3(pr, Q, Rm);
                #pragma unroll
                for (int i = 0; i < 9; i++) g_upd[i] = Q[i];
                #pragma unroll
                for (int i = 0; i < 3; i++) g_upd[9+i] = trv[i];
            }
        }
        gridbar(sense);   // updated params visible

        // ---- forward for step s+1 ----
        {
            const volatile float* up = g_upd;
            float q0=up[0],q1=up[1],q2=up[2],q3=up[3],q4=up[4],q5=up[5],q6=up[6],q7=up[7],q8=up[8];
            float t0=up[9],t1=up[10],t2=up[11];
            nx = q0*lx + q1*ly + q2*lz + t0;
            ny = q3*lx + q4*ly + q5*lz + t1;
            nz = q6*lx + q7*ly + q8*lz + t2;
            if (lane == 0) {
                float* o0 = out + (size_t)(s+1)*3*Lq + 3*l;
                o0[0]=nx; o0[1]=ny; o0[2]=nz;
            }
            nx2 = pk2(nx, nx); ny2 = pk2(ny, ny); nz2 = pk2(nz, nz);
        }
    }
}

extern "C" void kernel_launch(void* const* d_in, const int* in_sizes, int n_in,
                              void* d_out, int out_size) {
    const float* lig_feat  = (const float*)d_in[0];
    const float* rec_feat  = (const float*)d_in[1];
    const float* lig_coord = (const float*)d_in[2];
    const float* rec_coord = (const float*)d_in[3];
    const float* pre_rot   = (const float*)d_in[4];
    const float* trans     = (const float*)d_in[5];
    float* out = (float*)d_out;

    static bool attr_set = false;
    if (!attr_set) {
        cudaFuncSetAttribute(k_steps, cudaFuncAttributeMaxDynamicSharedMemorySize,
                             3 * Rr * (int)sizeof(float));
        attr_set = true;
    }

    k_atn<<<dim3(Rr/64, Lq/64), 256>>>(lig_feat, rec_feat);
    k_steps<<<NB, NT, 3 * Rr * sizeof(float)>>>(lig_coord, rec_coord, pre_rot, trans, out);
}